// round 13
// baseline (speedup 1.0000x reference)
#include <cuda_runtime.h>

#define NODES 100000
#define NEDGES 3200000
#define DD 20
#define BCAP 128   // bucket capacity per node; P(in-deg > 128) ~ 0 (Poisson mean 32)
#define GSTR 32    // padded row stride (floats): 128B-aligned rows, 1 L1 line/row

// ---------------- static device scratch (no allocations allowed) ----------------
__device__ int   d_cnt[2 * NODES];         // [0:N) in-deg (bucket fill), [N:2N) out-deg
__device__ int   d_col[NODES * BCAP];      // bucket CSR: node n's srcs at [n*BCAP, n*BCAP+cnt)
__device__ float d_din[NODES];
__device__ float d_dout[NODES];
__device__ float d_g0[NODES];
__device__ __align__(128) float d_gA[NODES * GSTR];   // activations g = h*dout (padded)
__device__ __align__(128) float d_gB[NODES * GSTR];
__device__ __align__(128) float d_y[NODES * GSTR];    // y = g @ W (padded)

// ---------------- graph build: single scatter pass (no hist, no scan) ----------
__global__ void k_scatter(const int* __restrict__ src, const int* __restrict__ dst) {
    int e = blockIdx.x * blockDim.x + threadIdx.x;
    if (e < NEDGES) {
        int s = src[e], d = dst[e];
        int p = atomicAdd(&d_cnt[d], 1);
        d_col[d * BCAP + p] = s;
        atomicAdd(&d_cnt[NODES + s], 1);   // out-degree count
    }
}

__global__ void k_init(const float* __restrict__ feat) {
    int i = blockIdx.x * blockDim.x + threadIdx.x;
    if (i < NODES) {
        float di = rsqrtf((float)(d_cnt[i] + 1));           // +1 self-loop
        float dq = rsqrtf((float)(d_cnt[NODES + i] + 1));
        d_din[i]  = di;
        d_dout[i] = dq;
        d_g0[i]   = feat[i] * dq;                           // layer-0 source values
    }
}

// ---------------- layer 0 : scalar aggregation, D_in = 1 ----------------
__global__ void __launch_bounds__(256)
k_layer0(const float* __restrict__ W, const float* __restrict__ b) {
    const unsigned FULL = 0xffffffffu;
    int lane = threadIdx.x & 31;
    int w    = (blockIdx.x * blockDim.x + threadIdx.x) >> 5;
    int nw   = (gridDim.x * blockDim.x) >> 5;
    int tt   = lane < DD ? lane : 0;
    float wt = W[tt];
    float bt = b[tt];
    for (int n = w; n < NODES; n += nw) {
        int beg = n * BCAP, end = beg + d_cnt[n];
        float acc = (lane == 0) ? d_g0[n] : 0.f;     // self-loop
        for (int j = beg + lane; j < end; j += 32)
            acc += __ldg(&d_g0[__ldg(&d_col[j])]);
        #pragma unroll
        for (int off = 16; off; off >>= 1)
            acc += __shfl_xor_sync(FULL, acc, off);
        if (lane < DD) {
            float r = fmaf(d_din[n] * acc, wt, bt);
            r = fmaxf(r, 0.f);
            d_gA[n * GSTR + lane] = r * d_dout[n];   // g = h*dout (padded row)
        }
    }
}

// ---------------- dense pre-multiply: y = g @ W (per node, 20x20) -------------
__global__ void __launch_bounds__(256)
k_dense(const float* __restrict__ gin, float* __restrict__ yout,
        const float* __restrict__ W) {
    __shared__ float Wsm[DD * DD];
    for (int i = threadIdx.x; i < DD * DD; i += blockDim.x) Wsm[i] = W[i];
    __syncthreads();

    int n = blockIdx.x * blockDim.x + threadIdx.x;
    if (n >= NODES) return;

    const float4* grow = (const float4*)(gin + n * GSTR);
    float s[DD];
    #pragma unroll
    for (int q = 0; q < 5; q++) {
        float4 v = __ldg(&grow[q]);
        s[4 * q + 0] = v.x; s[4 * q + 1] = v.y; s[4 * q + 2] = v.z; s[4 * q + 3] = v.w;
    }
    float o[DD];
    #pragma unroll
    for (int k = 0; k < DD; k++) o[k] = 0.f;
    #pragma unroll
    for (int j = 0; j < DD; j++) {
        float sj = s[j];
        #pragma unroll
        for (int k = 0; k < DD; k++)
            o[k] = fmaf(sj, Wsm[j * DD + k], o[k]);
    }
    float4* yrow = (float4*)(yout + n * GSTR);
    #pragma unroll
    for (int q = 0; q < 5; q++) {
        float4 v;
        v.x = o[4 * q + 0]; v.y = o[4 * q + 1]; v.z = o[4 * q + 2]; v.w = o[4 * q + 3];
        yrow[q] = v;
    }
}

// ---------------- aggregation (lane = feature) + elementwise epilogue ----------
// Each edge: broadcast index, ALL lanes load from the SAME padded row -> exactly
// one L1 line per LDG instruction (1.0 cyc/wavefront, no within-LDG replays).
// No cross-lane reduction at all. Rows batched 8-deep for MLP.
template <int RELU, int SCALE, int PACKED>
__global__ void __launch_bounds__(256)
k_agg(const float* __restrict__ yin, float* __restrict__ gout,
      const float* __restrict__ b) {
    const unsigned FULL = 0xffffffffu;
    int lane = threadIdx.x & 31;
    int w    = (blockIdx.x * blockDim.x + threadIdx.x) >> 5;
    int nw   = (gridDim.x * blockDim.x) >> 5;
    bool act = lane < DD;
    float bt = act ? __ldg(&b[lane]) : 0.f;

    for (int n = w; n < NODES; n += nw) {
        int beg = n * BCAP;
        int cnt = __ldg(&d_cnt[n]);
        // self-loop: lane tt accumulates feature tt (lanes 20-31 track padding, unused)
        float acc  = __ldg(&yin[(n << 5) + lane]);
        float acc2 = 0.f;

        for (int base = 0; base < cnt; base += 32) {
            // 32 neighbor indices in ONE coalesced 128B line (bucket is 128B-aligned)
            int idx = __ldg(&d_col[beg + base + lane]);
            int m = cnt - base; if (m > 32) m = 32;    // warp-uniform
            int e = 0;
            for (; e + 8 <= m; e += 8) {               // 8 rows in flight
                int s0 = __shfl_sync(FULL, idx, e + 0);
                int s1 = __shfl_sync(FULL, idx, e + 1);
                int s2 = __shfl_sync(FULL, idx, e + 2);
                int s3 = __shfl_sync(FULL, idx, e + 3);
                int s4 = __shfl_sync(FULL, idx, e + 4);
                int s5 = __shfl_sync(FULL, idx, e + 5);
                int s6 = __shfl_sync(FULL, idx, e + 6);
                int s7 = __shfl_sync(FULL, idx, e + 7);
                float v0 = __ldg(&yin[(s0 << 5) + lane]);
                float v1 = __ldg(&yin[(s1 << 5) + lane]);
                float v2 = __ldg(&yin[(s2 << 5) + lane]);
                float v3 = __ldg(&yin[(s3 << 5) + lane]);
                float v4 = __ldg(&yin[(s4 << 5) + lane]);
                float v5 = __ldg(&yin[(s5 << 5) + lane]);
                float v6 = __ldg(&yin[(s6 << 5) + lane]);
                float v7 = __ldg(&yin[(s7 << 5) + lane]);
                acc  += v0; acc2 += v1;
                acc  += v2; acc2 += v3;
                acc  += v4; acc2 += v5;
                acc  += v6; acc2 += v7;
            }
            for (; e < m; e++) {                       // tail (< 8 edges)
                int s = __shfl_sync(FULL, idx, e);
                acc += __ldg(&yin[(s << 5) + lane]);
            }
        }

        float s = acc + acc2;
        if (act) {
            float din = __ldg(&d_din[n]);
            float r = fmaf(din, s, bt);
            if (RELU)  r = fmaxf(r, 0.f);
            if (SCALE) r *= __ldg(&d_dout[n]);
            if (PACKED) gout[n * DD + lane] = r;       // final: packed fp32 rows
            else        gout[(n << 5) + lane] = r;     // mids: padded rows (1 line)
        }
    }
}

// ---------------- launch ----------------
#define L0GRID 1184
#define AGRID  1184
#define DGRID  ((NODES + 255) / 256)

extern "C" void kernel_launch(void* const* d_in, const int* in_sizes, int n_in,
                              void* d_out, int out_size) {
    const float* feat = (const float*)d_in[0];
    const float* Ws   = (const float*)d_in[1];
    const float* bs   = (const float*)d_in[2];
    const float* Wm   = (const float*)d_in[3];
    const float* bm   = (const float*)d_in[4];
    const float* Wf   = (const float*)d_in[5];
    const float* bf   = (const float*)d_in[6];
    const int*   src  = (const int*)d_in[7];
    const int*   dst  = (const int*)d_in[8];
    float* out = (float*)d_out;

    // resolve device-symbol addresses (host API, capture-safe)
    void *pA, *pB, *pY, *pCnt;
    cudaGetSymbolAddress(&pA, d_gA);
    cudaGetSymbolAddress(&pB, d_gB);
    cudaGetSymbolAddress(&pY, d_y);
    cudaGetSymbolAddress(&pCnt, d_cnt);
    float* gA = (float*)pA;
    float* gB = (float*)pB;
    float* y  = (float*)pY;

    // zero degree counters (async memset: graph-capturable)
    cudaMemsetAsync(pCnt, 0, 2 * NODES * sizeof(int));

    // build: ONE scatter pass into fixed-capacity buckets, then per-node init
    k_scatter<<<(NEDGES + 255) / 256, 256>>>(src, dst);
    k_init   <<<(NODES  + 255) / 256, 256>>>(feat);

    // layer 0 (scalar gather, fused W_start)
    k_layer0<<<L0GRID, 256>>>(Ws, bs);               // writes gA (padded)

    // 18 mid layers: dense y = g@W, then gather+epilogue
    int cur = 0;                                      // activations in gA when cur==0
    for (int k = 0; k < 18; k++) {
        const float* gin = cur ? gB : gA;
        float* gnext     = cur ? gA : gB;
        k_dense<<<DGRID, 256>>>(gin, y, Wm + k * DD * DD);
        k_agg<1, 1, 0><<<AGRID, 256>>>(y, gnext, bm + k * DD);
        cur ^= 1;
    }
    // final layer: no relu, no dout scale, packed fp32 output
    const float* gin = cur ? gB : gA;
    k_dense<<<DGRID, 256>>>(gin, y, Wf);
    k_agg<0, 0, 1><<<AGRID, 256>>>(y, out, bf);
}

// round 14
// speedup vs baseline: 1.0898x; 1.0898x over previous
#include <cuda_runtime.h>

#define NODES 100000
#define NEDGES 3200000
#define DD 20
#define BCAP 128   // bucket capacity per node; P(in-deg > 128) ~ 0 (Poisson mean 32)
#define GSTR 32    // padded row stride (floats): 128B-aligned rows, 1 L1 line/row

// ---------------- static device scratch (no allocations allowed) ----------------
__device__ int   d_cnt[2 * NODES];         // [0:N) in-deg (bucket fill), [N:2N) out-deg
__device__ int   d_col[NODES * BCAP];      // bucket CSR: node n's srcs at [n*BCAP, n*BCAP+cnt)
__device__ float d_din[NODES];
__device__ float d_dout[NODES];
__device__ float d_g0[NODES];
__device__ __align__(128) float d_gA[NODES * GSTR];   // activations g = h*dout (padded)
__device__ __align__(128) float d_gB[NODES * GSTR];

// ---------------- graph build: single scatter pass (no hist, no scan) ----------
__global__ void k_scatter(const int* __restrict__ src, const int* __restrict__ dst) {
    int e = blockIdx.x * blockDim.x + threadIdx.x;
    if (e < NEDGES) {
        int s = src[e], d = dst[e];
        int p = atomicAdd(&d_cnt[d], 1);
        d_col[d * BCAP + p] = s;
        atomicAdd(&d_cnt[NODES + s], 1);   // out-degree count
    }
}

__global__ void k_init(const float* __restrict__ feat) {
    int i = blockIdx.x * blockDim.x + threadIdx.x;
    if (i < NODES) {
        float di = rsqrtf((float)(d_cnt[i] + 1));           // +1 self-loop
        float dq = rsqrtf((float)(d_cnt[NODES + i] + 1));
        d_din[i]  = di;
        d_dout[i] = dq;
        d_g0[i]   = feat[i] * dq;                           // layer-0 source values
    }
}

// ---------------- layer 0 : scalar aggregation, D_in = 1 ----------------
__global__ void __launch_bounds__(256)
k_layer0(const float* __restrict__ W, const float* __restrict__ b) {
    const unsigned FULL = 0xffffffffu;
    int lane = threadIdx.x & 31;
    int w    = (blockIdx.x * blockDim.x + threadIdx.x) >> 5;
    int nw   = (gridDim.x * blockDim.x) >> 5;
    int tt   = lane < DD ? lane : 0;
    float wt = W[tt];
    float bt = b[tt];
    for (int n = w; n < NODES; n += nw) {
        int beg = n * BCAP, end = beg + d_cnt[n];
        float acc = (lane == 0) ? d_g0[n] : 0.f;     // self-loop
        for (int j = beg + lane; j < end; j += 32)
            acc += __ldg(&d_g0[__ldg(&d_col[j])]);
        #pragma unroll
        for (int off = 16; off; off >>= 1)
            acc += __shfl_xor_sync(FULL, acc, off);
        if (lane < DD) {
            float r = fmaf(d_din[n] * acc, wt, bt);
            r = fmaxf(r, 0.f);
            d_gA[n * GSTR + lane] = r * d_dout[n];   // g = h*dout (padded row)
        }
    }
}

// ---------------- fused layer, lane = feature -----------------------------------
// Aggregation: per edge, ALL lanes load the SAME padded row (warp-uniform index
// loaded by all lanes from d_col — uniform LDG, L1-resident). Each row-LDG touches
// exactly ONE 128B line => cross-LDG wavefront rate (1.0 cyc), no replays, and the
// cross-lane reduction disappears (lane j owns feature j's partial sum).
// Then matvec via 20 shfl-broadcasts with W column in registers (R11-proven).
template <int RELU, int SCALE, int OSTR>
__device__ __forceinline__ void layer_body(const float* __restrict__ gin,
                                           float* __restrict__ gout,
                                           const float* __restrict__ W,
                                           const float* __restrict__ b) {
    const unsigned FULL = 0xffffffffu;
    int lane = threadIdx.x & 31;
    int w    = (blockIdx.x * blockDim.x + threadIdx.x) >> 5;
    int nw   = (gridDim.x * blockDim.x) >> 5;
    int tt   = lane < DD ? lane : 0;
    float wcol[DD];
    #pragma unroll
    for (int k = 0; k < DD; k++) wcol[k] = W[k * DD + tt];
    float bt = b[tt];

    for (int n = w; n < NODES; n += nw) {
        int beg = n * BCAP;
        int cnt = __ldg(&d_cnt[n]);
        // self-loop: lane j accumulates feature j (lanes 20-31 read padding, never used)
        float acc  = __ldg(&gin[(n << 5) + lane]);
        float acc2 = 0.f;

        // ---- main loop: 8 edges / body, 8 independent row-chains in flight ----
        int e = 0;
        for (; e + 8 <= cnt; e += 8) {
            int q = beg + e;
            int s0 = __ldg(&d_col[q + 0]);   // warp-uniform addr: 1 wavefront, L1-hot
            int s1 = __ldg(&d_col[q + 1]);
            int s2 = __ldg(&d_col[q + 2]);
            int s3 = __ldg(&d_col[q + 3]);
            int s4 = __ldg(&d_col[q + 4]);
            int s5 = __ldg(&d_col[q + 5]);
            int s6 = __ldg(&d_col[q + 6]);
            int s7 = __ldg(&d_col[q + 7]);
            float v0 = __ldg(&gin[(s0 << 5) + lane]);   // 1 line per LDG
            float v1 = __ldg(&gin[(s1 << 5) + lane]);
            float v2 = __ldg(&gin[(s2 << 5) + lane]);
            float v3 = __ldg(&gin[(s3 << 5) + lane]);
            float v4 = __ldg(&gin[(s4 << 5) + lane]);
            float v5 = __ldg(&gin[(s5 << 5) + lane]);
            float v6 = __ldg(&gin[(s6 << 5) + lane]);
            float v7 = __ldg(&gin[(s7 << 5) + lane]);
            acc  += v0; acc2 += v1;
            acc  += v2; acc2 += v3;
            acc  += v4; acc2 += v5;
            acc  += v6; acc2 += v7;
        }
        // ---- remainder: < 8 edges ----
        for (; e < cnt; e++) {
            int s = __ldg(&d_col[beg + e]);
            acc += __ldg(&gin[(s << 5) + lane]);
        }
        acc += acc2;   // lane j now holds s[j] (j < 20)

        // matvec: out[tt] = sum_k s[k] * W[k][tt]  (broadcast s[k] from lane k)
        float m = 0.f;
        #pragma unroll
        for (int k = 0; k < DD; k++)
            m = fmaf(__shfl_sync(FULL, acc, k), wcol[k], m);

        if (lane < DD) {
            float r = fmaf(__ldg(&d_din[n]), m, bt);
            if (RELU)  r = fmaxf(r, 0.f);
            if (SCALE) r *= __ldg(&d_dout[n]);
            gout[n * OSTR + lane] = r;
        }
    }
}

__global__ void __launch_bounds__(256, 4)
k_layer_mid(const float* __restrict__ W, const float* __restrict__ b, int cur) {
    const float* gin = cur ? d_gB : d_gA;
    float* gout      = cur ? d_gA : d_gB;
    layer_body<1, 1, GSTR>(gin, gout, W, b);
}

__global__ void __launch_bounds__(256, 4)
k_layer_final(const float* __restrict__ W, const float* __restrict__ b,
              int cur, float* __restrict__ out) {
    const float* gin = cur ? d_gB : d_gA;
    layer_body<0, 0, DD>(gin, out, W, b);
}

// ---------------- launch ----------------
#define L0GRID 1184
#define MGRID  1184

extern "C" void kernel_launch(void* const* d_in, const int* in_sizes, int n_in,
                              void* d_out, int out_size) {
    const float* feat = (const float*)d_in[0];
    const float* Ws   = (const float*)d_in[1];
    const float* bs   = (const float*)d_in[2];
    const float* Wm   = (const float*)d_in[3];
    const float* bm   = (const float*)d_in[4];
    const float* Wf   = (const float*)d_in[5];
    const float* bf   = (const float*)d_in[6];
    const int*   src  = (const int*)d_in[7];
    const int*   dst  = (const int*)d_in[8];
    float* out = (float*)d_out;

    // zero degree counters (async memset: graph-capturable)
    void* p_cnt = nullptr;
    cudaGetSymbolAddress(&p_cnt, d_cnt);
    cudaMemsetAsync(p_cnt, 0, 2 * NODES * sizeof(int));

    // build: ONE scatter pass into fixed-capacity buckets, then per-node init
    k_scatter<<<(NEDGES + 255) / 256, 256>>>(src, dst);
    k_init   <<<(NODES  + 255) / 256, 256>>>(feat);

    // 20 conv layers, one fused kernel each
    k_layer0<<<L0GRID, 256>>>(Ws, bs);               // writes d_gA (padded)
    int cur = 0;
    for (int k = 0; k < 18; k++) {
        k_layer_mid<<<MGRID, 256>>>(Wm + k * DD * DD, bm + k * DD, cur);
        cur ^= 1;
    }
    k_layer_final<<<MGRID, 256>>>(Wf, bf, cur, out);
}

// round 15
// speedup vs baseline: 1.4008x; 1.2853x over previous
#include <cuda_runtime.h>

#define NODES 100000
#define NEDGES 3200000
#define DD 20
#define BCAP 128   // bucket capacity per node; P(in-deg > 128) ~ 0 (Poisson mean 32)
#define GSTR 32    // padded row stride (floats): 128B-aligned rows, 1 L1 line/row

// ---------------- static device scratch (no allocations allowed) ----------------
__device__ int   d_cnt[2 * NODES];         // [0:N) in-deg (bucket fill), [N:2N) out-deg
__device__ int   d_col[NODES * BCAP];      // bucket CSR: node n's srcs at [n*BCAP, n*BCAP+cnt)
__device__ float d_din[NODES];
__device__ float d_dout[NODES];
__device__ float d_g0[NODES];
__device__ __align__(128) float d_gA[NODES * GSTR];   // activations g = h*dout (padded)
__device__ __align__(128) float d_gB[NODES * GSTR];

// ---------------- graph build: single scatter pass (no hist, no scan) ----------
__global__ void k_scatter(const int* __restrict__ src, const int* __restrict__ dst) {
    int e = blockIdx.x * blockDim.x + threadIdx.x;
    if (e < NEDGES) {
        int s = src[e], d = dst[e];
        int p = atomicAdd(&d_cnt[d], 1);
        d_col[d * BCAP + p] = s;
        atomicAdd(&d_cnt[NODES + s], 1);   // out-degree count
    }
}

__global__ void k_init(const float* __restrict__ feat) {
    int i = blockIdx.x * blockDim.x + threadIdx.x;
    if (i < NODES) {
        float di = rsqrtf((float)(d_cnt[i] + 1));           // +1 self-loop
        float dq = rsqrtf((float)(d_cnt[NODES + i] + 1));
        d_din[i]  = di;
        d_dout[i] = dq;
        d_g0[i]   = feat[i] * dq;                           // layer-0 source values
    }
}

// ---------------- layer 0 : scalar aggregation, D_in = 1 ----------------
__global__ void __launch_bounds__(256)
k_layer0(const float* __restrict__ W, const float* __restrict__ b) {
    const unsigned FULL = 0xffffffffu;
    int lane = threadIdx.x & 31;
    int w    = (blockIdx.x * blockDim.x + threadIdx.x) >> 5;
    int nw   = (gridDim.x * blockDim.x) >> 5;
    int tt   = lane < DD ? lane : 0;
    float wt = W[tt];
    float bt = b[tt];
    for (int n = w; n < NODES; n += nw) {
        int beg = n * BCAP, end = beg + d_cnt[n];
        float acc = (lane == 0) ? d_g0[n] : 0.f;     // self-loop
        for (int j = beg + lane; j < end; j += 32)
            acc += __ldg(&d_g0[__ldg(&d_col[j])]);
        #pragma unroll
        for (int off = 16; off; off >>= 1)
            acc += __shfl_xor_sync(FULL, acc, off);
        if (lane < DD) {
            float r = fmaf(d_din[n] * acc, wt, bt);
            r = fmaxf(r, 0.f);
            d_gA[n * GSTR + lane] = r * d_dout[n];   // g = h*dout (padded row)
        }
    }
}

// ---------------- fused layer: aggregate(g) -> @W -> *din +b -> (relu) -> (*dout) ----
// R11 champion structure; single change: ONE warp-uniform predicated gather loop
// (4-deep, 24 edges/block) replaces main-body + serial 2-deep remainder.
template <int RELU, int SCALE, int OSTR>
__device__ __forceinline__ void layer_body(const float* __restrict__ gin,
                                           float* __restrict__ gout,
                                           const float* __restrict__ W,
                                           const float* __restrict__ b) {
    const unsigned FULL = 0xffffffffu;
    int lane = threadIdx.x & 31;
    int w    = (blockIdx.x * blockDim.x + threadIdx.x) >> 5;
    int nw   = (gridDim.x * blockDim.x) >> 5;
    // lane layout for aggregation: 6 edges x 5 float4 chunks (lanes 30,31 idle)
    int c    = lane % 5;
    int esub = lane / 5;
    bool lok = lane < 30;
    int tt = lane < DD ? lane : 0;
    float wcol[DD];
    #pragma unroll
    for (int k = 0; k < DD; k++) wcol[k] = W[k * DD + tt];
    float bt = b[tt];
    const float4* gin4 = (const float4*)gin;   // 8 float4 per padded row (first 5 used)

    for (int n = w; n < NODES; n += nw) {
        int beg = n * BCAP, end = beg + __ldg(&d_cnt[n]);
        float4 acc  = make_float4(0.f, 0.f, 0.f, 0.f);
        float4 acc2 = make_float4(0.f, 0.f, 0.f, 0.f);
        if (lok && esub == 0) acc = __ldg(&gin4[(n << 3) + c]);   // self-loop

        // ---- ONE uniform loop: predicated 4-deep blocks of 24 edges ----
        for (int j0 = beg; j0 < end; j0 += 24) {
            int jj = j0 + esub;
            bool p0 = lok && (jj      < end);
            bool p1 = lok && (jj + 6  < end);
            bool p2 = lok && (jj + 12 < end);
            bool p3 = lok && (jj + 18 < end);
            int s0 = 0, s1 = 0, s2 = 0, s3 = 0;
            if (p0) s0 = __ldg(&d_col[jj]);
            if (p1) s1 = __ldg(&d_col[jj + 6]);
            if (p2) s2 = __ldg(&d_col[jj + 12]);
            if (p3) s3 = __ldg(&d_col[jj + 18]);
            float4 x0 = make_float4(0.f, 0.f, 0.f, 0.f);
            float4 x1 = make_float4(0.f, 0.f, 0.f, 0.f);
            float4 x2 = make_float4(0.f, 0.f, 0.f, 0.f);
            float4 x3 = make_float4(0.f, 0.f, 0.f, 0.f);
            if (p0) x0 = __ldg(&gin4[(s0 << 3) + c]);
            if (p1) x1 = __ldg(&gin4[(s1 << 3) + c]);
            if (p2) x2 = __ldg(&gin4[(s2 << 3) + c]);
            if (p3) x3 = __ldg(&gin4[(s3 << 3) + c]);
            acc.x  += x0.x; acc.y  += x0.y; acc.z  += x0.z; acc.w  += x0.w;
            acc2.x += x1.x; acc2.y += x1.y; acc2.z += x1.z; acc2.w += x1.w;
            acc.x  += x2.x; acc.y  += x2.y; acc.z  += x2.z; acc.w  += x2.w;
            acc2.x += x3.x; acc2.y += x3.y; acc2.z += x3.z; acc2.w += x3.w;
        }
        acc.x += acc2.x; acc.y += acc2.y; acc.z += acc2.z; acc.w += acc2.w;

        // Reduce the 6 edge groups (stride 5), predicated folds (no double count):
        float4 t;
        t.x = __shfl_down_sync(FULL, acc.x, 15);
        t.y = __shfl_down_sync(FULL, acc.y, 15);
        t.z = __shfl_down_sync(FULL, acc.z, 15);
        t.w = __shfl_down_sync(FULL, acc.w, 15);
        if (lane < 15) { acc.x += t.x; acc.y += t.y; acc.z += t.z; acc.w += t.w; }
        t.x = __shfl_down_sync(FULL, acc.x, 10);
        t.y = __shfl_down_sync(FULL, acc.y, 10);
        t.z = __shfl_down_sync(FULL, acc.z, 10);
        t.w = __shfl_down_sync(FULL, acc.w, 10);
        if (lane < 5) { acc.x += t.x; acc.y += t.y; acc.z += t.z; acc.w += t.w; }
        t.x = __shfl_down_sync(FULL, acc.x, 5);
        t.y = __shfl_down_sync(FULL, acc.y, 5);
        t.z = __shfl_down_sync(FULL, acc.z, 5);
        t.w = __shfl_down_sync(FULL, acc.w, 5);
        if (lane < 5) { acc.x += t.x; acc.y += t.y; acc.z += t.z; acc.w += t.w; }

        // lane c holds s[4c..4c+3]; broadcast + matvec out[tt] = sum_k s[k]*W[k][tt]
        float m = 0.f;
        #pragma unroll
        for (int k = 0; k < DD; k++) {
            float comp = ((k & 3) == 0) ? acc.x :
                         ((k & 3) == 1) ? acc.y :
                         ((k & 3) == 2) ? acc.z : acc.w;
            float sk = __shfl_sync(FULL, comp, k >> 2);
            m = fmaf(sk, wcol[k], m);
        }
        if (lane < DD) {
            float r = fmaf(__ldg(&d_din[n]), m, bt);
            if (RELU)  r = fmaxf(r, 0.f);
            if (SCALE) r *= __ldg(&d_dout[n]);
            gout[n * OSTR + lane] = r;
        }
    }
}

__global__ void __launch_bounds__(256, 4)
k_layer_mid(const float* __restrict__ W, const float* __restrict__ b, int cur) {
    const float* gin = cur ? d_gB : d_gA;
    float* gout      = cur ? d_gA : d_gB;
    layer_body<1, 1, GSTR>(gin, gout, W, b);
}

__global__ void __launch_bounds__(256, 4)
k_layer_final(const float* __restrict__ W, const float* __restrict__ b,
              int cur, float* __restrict__ out) {
    const float* gin = cur ? d_gB : d_gA;
    layer_body<0, 0, DD>(gin, out, W, b);
}

// ---------------- launch ----------------
#define L0GRID 1184    // layer0: 26 regs -> 8 blocks/SM
#define MGRID  592     // mids: reg-capped 4 blocks/SM -> one exact wave

extern "C" void kernel_launch(void* const* d_in, const int* in_sizes, int n_in,
                              void* d_out, int out_size) {
    const float* feat = (const float*)d_in[0];
    const float* Ws   = (const float*)d_in[1];
    const float* bs   = (const float*)d_in[2];
    const float* Wm   = (const float*)d_in[3];
    const float* bm   = (const float*)d_in[4];
    const float* Wf   = (const float*)d_in[5];
    const float* bf   = (const float*)d_in[6];
    const int*   src  = (const int*)d_in[7];
    const int*   dst  = (const int*)d_in[8];
    float* out = (float*)d_out;

    // zero degree counters (async memset: graph-capturable)
    void* p_cnt = nullptr;
    cudaGetSymbolAddress(&p_cnt, d_cnt);
    cudaMemsetAsync(p_cnt, 0, 2 * NODES * sizeof(int));

    // build: ONE scatter pass into fixed-capacity buckets, then per-node init
    k_scatter<<<(NEDGES + 255) / 256, 256>>>(src, dst);   // launch 0
    k_init   <<<(NODES  + 255) / 256, 256>>>(feat);       // launch 1

    // 20 conv layers, one fused kernel each
    k_layer0<<<L0GRID, 256>>>(Ws, bs);                    // launch 2, writes d_gA
    int cur = 0;
    for (int k = 0; k < 18; k++) {
        k_layer_mid<<<MGRID, 256>>>(Wm + k * DD * DD, bm + k * DD, cur);  // launch 3+ profiled
        cur ^= 1;
    }
    k_layer_final<<<MGRID, 256>>>(Wf, bf, cur, out);
}